// round 2
// baseline (speedup 1.0000x reference)
#include <cuda_runtime.h>
#include <cstdint>

// Problem constants
#define BATCH 8
#define NPTS  8192
#define SA    2048   // xyz2_a / points2_a
#define SB    512    // xyz2_b / points2_b
#define C1    128
#define C2    256
#define INCH  640    // C1 + 2*C2
#define ROWS  (BATCH * NPTS)   // 65536
#define NCHUNKS 256
#define ROWS_PER_CHUNK (ROWS / NCHUNKS)  // 256

// ---------------- scratch (device globals; no runtime alloc allowed) ----------------
__device__ float g_x0[(size_t)ROWS * INCH];      // concat features [row][640]
__device__ float g_bufA[(size_t)ROWS * 256];
__device__ float g_bufB[(size_t)ROWS * 256];
__device__ float g_p2at[(size_t)BATCH * SA * C2]; // transposed points2_a [b][s][c]
__device__ float g_p2bt[(size_t)BATCH * SB * C2]; // transposed points2_b
__device__ int   g_idxA[(size_t)ROWS * 3];
__device__ float g_wA[(size_t)ROWS * 3];
__device__ int   g_idxB[(size_t)ROWS * 3];
__device__ float g_wB[(size_t)ROWS * 3];
__device__ float g_part_sum[NCHUNKS * 256];
__device__ float g_part_sq[NCHUNKS * 256];
__device__ float g_scale[256];
__device__ float g_shift[256];

// Buffer selectors so host code never needs device addresses of globals.
__device__ __forceinline__ float* buf_ptr(int which) {
    return which == 0 ? g_bufA : g_bufB;
}

// ---------------- transpose [B][C][Nn] -> dst[(b*Nn+n)*ldo + co + c] ----------------
// dst: 0 = g_x0, 1 = g_p2at, 2 = g_p2bt
__global__ void transpose_cn(const float* __restrict__ in, int dst,
                             int C, int Nn, int ldo, int co) {
    __shared__ float tile[32][33];
    float* out = (dst == 0) ? g_x0 : (dst == 1 ? g_p2at : g_p2bt);
    int b = blockIdx.z;
    int n0 = blockIdx.x * 32;
    int c0 = blockIdx.y * 32;
    int x = threadIdx.x, y = threadIdx.y; // block (32,8)
    const float* inb = in + (size_t)b * C * Nn;
#pragma unroll
    for (int i = 0; i < 32; i += 8) {
        int c = c0 + y + i;
        tile[y + i][x] = inb[(size_t)c * Nn + n0 + x];
    }
    __syncthreads();
    float* outb = out + (size_t)b * Nn * ldo + co;
#pragma unroll
    for (int i = 0; i < 32; i += 8) {
        int n = n0 + y + i;
        outb[(size_t)n * ldo + c0 + x] = tile[x][y + i];
    }
}

// ---------------- 3-NN: for each query, 3 smallest squared distances ----------------
template <int S>
__global__ void knn3_kernel(const float* __restrict__ xyz1, const float* __restrict__ xyz2,
                            int* __restrict__ idx_out, float* __restrict__ w_out) {
    __shared__ float rx[S], ry[S], rz[S], rsq[S];
    int b = blockIdx.y;
    int n = blockIdx.x * blockDim.x + threadIdx.x;
    const float* x2 = xyz2 + (size_t)b * 3 * S;
    for (int s = threadIdx.x; s < S; s += blockDim.x) {
        float a = x2[s], bb = x2[S + s], c = x2[2 * S + s];
        rx[s] = a; ry[s] = bb; rz[s] = c;
        rsq[s] = a * a + bb * bb + c * c;
    }
    __syncthreads();
    const float* x1 = xyz1 + (size_t)b * 3 * NPTS;
    float qx = x1[n], qy = x1[NPTS + n], qz = x1[2 * NPTS + n];
    float qn = qx * qx + qy * qy + qz * qz;
    float d0 = 1e30f, d1 = 1e30f, d2 = 1e30f;
    int i0 = 0, i1 = 0, i2 = 0;
#pragma unroll 4
    for (int s = 0; s < S; s++) {
        float dot = qx * rx[s] + qy * ry[s] + qz * rz[s];
        float d = qn + rsq[s] - 2.0f * dot;   // same expansion as reference
        if (d < d2) {
            if (d < d1) {
                d2 = d1; i2 = i1;
                if (d < d0) { d1 = d0; i1 = i0; d0 = d; i0 = s; }
                else        { d1 = d;  i1 = s; }
            } else { d2 = d; i2 = s; }
        }
    }
    float r0 = 1.0f / (d0 + 1e-8f), r1 = 1.0f / (d1 + 1e-8f), r2 = 1.0f / (d2 + 1e-8f);
    float inv = 1.0f / (r0 + r1 + r2);
    size_t base = ((size_t)b * NPTS + n) * 3;
    idx_out[base] = i0; idx_out[base + 1] = i1; idx_out[base + 2] = i2;
    w_out[base] = r0 * inv; w_out[base + 1] = r1 * inv; w_out[base + 2] = r2 * inv;
}

// ---- thin launchers for knn so host passes only harness pointers ----
__global__ void knn3_a(const float* __restrict__ xyz1, const float* __restrict__ xyz2);
__global__ void knn3_b(const float* __restrict__ xyz1, const float* __restrict__ xyz2);

// ------------- gather: weighted 3-NN feature sums into x0 cols [128,640) -------------
__global__ void gather_interp() {
    int r = blockIdx.x;           // row (b*N + n)
    int c = threadIdx.x;          // 0..255 channel
    int b = r / NPTS;
    size_t nb = (size_t)r * 3;
    int ib0 = g_idxB[nb], ib1 = g_idxB[nb + 1], ib2 = g_idxB[nb + 2];
    float vb0 = g_wB[nb], vb1 = g_wB[nb + 1], vb2 = g_wB[nb + 2];
    int ia0 = g_idxA[nb], ia1 = g_idxA[nb + 1], ia2 = g_idxA[nb + 2];
    float va0 = g_wA[nb], va1 = g_wA[nb + 1], va2 = g_wA[nb + 2];
    const float* pb = g_p2bt + (size_t)b * SB * C2;
    const float* pa = g_p2at + (size_t)b * SA * C2;
    float ob = vb0 * pb[(size_t)ib0 * C2 + c] + vb1 * pb[(size_t)ib1 * C2 + c]
             + vb2 * pb[(size_t)ib2 * C2 + c];
    float oa = va0 * pa[(size_t)ia0 * C2 + c] + va1 * pa[(size_t)ia1 * C2 + c]
             + va2 * pa[(size_t)ia2 * C2 + c];
    size_t rb = (size_t)r * INCH;
    g_x0[rb + C1 + c]      = ob;   // interp_b  (source with S2=512)
    g_x0[rb + C1 + C2 + c] = oa;   // interp_a  (source with S1=2048)
}

// ------------- SGEMM: Y[M,Ncols] = X[M,K] @ W[Ncols,K]^T + bias -------------
// 128x128 tile, BK=8, 256 threads, 8x8 per thread.
// src: -1 = g_x0, 0 = g_bufA, 1 = g_bufB ; dstbuf: 0 = g_bufA, 1 = g_bufB
__global__ __launch_bounds__(256, 2)
void gemm_bias(int src, const float* __restrict__ W,
               const float* __restrict__ bias, int dstbuf,
               int K, int Ncols) {
    __shared__ float As[8][128];
    __shared__ float Bs[8][128];
    const float* X = (src < 0) ? g_x0 : buf_ptr(src);
    float* Y = buf_ptr(dstbuf);
    int tid = threadIdx.x;
    int row0 = blockIdx.y * 128;
    int col0 = blockIdx.x * 128;
    int tx = tid % 16, ty = tid / 16;
    int lr = tid >> 1;            // 0..127
    int lk = (tid & 1) * 4;       // 0 or 4
    float acc[8][8] = {};
    const float* Xp = X + (size_t)(row0 + lr) * K + lk;
    const float* Wp = W + (size_t)(col0 + lr) * K + lk;
    for (int k0 = 0; k0 < K; k0 += 8) {
        float4 xa = *(const float4*)(Xp + k0);
        float4 wb = *(const float4*)(Wp + k0);
        As[lk + 0][lr] = xa.x; As[lk + 1][lr] = xa.y;
        As[lk + 2][lr] = xa.z; As[lk + 3][lr] = xa.w;
        Bs[lk + 0][lr] = wb.x; Bs[lk + 1][lr] = wb.y;
        Bs[lk + 2][lr] = wb.z; Bs[lk + 3][lr] = wb.w;
        __syncthreads();
#pragma unroll
        for (int kk = 0; kk < 8; kk++) {
            float a[8], bv[8];
            *(float4*)&a[0]  = *(const float4*)&As[kk][ty * 8];
            *(float4*)&a[4]  = *(const float4*)&As[kk][ty * 8 + 4];
            *(float4*)&bv[0] = *(const float4*)&Bs[kk][tx * 8];
            *(float4*)&bv[4] = *(const float4*)&Bs[kk][tx * 8 + 4];
#pragma unroll
            for (int i = 0; i < 8; i++)
#pragma unroll
                for (int j = 0; j < 8; j++)
                    acc[i][j] = fmaf(a[i], bv[j], acc[i][j]);
        }
        __syncthreads();
    }
    float bv[8];
#pragma unroll
    for (int j = 0; j < 8; j++) bv[j] = bias[col0 + tx * 8 + j];
#pragma unroll
    for (int i = 0; i < 8; i++) {
        size_t rr = (size_t)(row0 + ty * 8 + i) * Ncols + col0 + tx * 8;
        float4 v0 = make_float4(acc[i][0] + bv[0], acc[i][1] + bv[1],
                                acc[i][2] + bv[2], acc[i][3] + bv[3]);
        float4 v1 = make_float4(acc[i][4] + bv[4], acc[i][5] + bv[5],
                                acc[i][6] + bv[6], acc[i][7] + bv[7]);
        *(float4*)&Y[rr]     = v0;
        *(float4*)&Y[rr + 4] = v1;
    }
}

// ------------- BN stats, deterministic 2-stage reduction -------------
__global__ void bn_partial(int srcbuf, int C) {
    const float* Y = buf_ptr(srcbuf);
    int c = threadIdx.x;         // blockDim = C
    int chunk = blockIdx.x;      // NCHUNKS
    size_t r0 = (size_t)chunk * ROWS_PER_CHUNK;
    float s = 0.f, sq = 0.f;
    for (int i = 0; i < ROWS_PER_CHUNK; i++) {
        float v = Y[(r0 + i) * C + c];
        s += v; sq += v * v;
    }
    g_part_sum[chunk * 256 + c] = s;
    g_part_sq[chunk * 256 + c] = sq;
}

__global__ void bn_finalize(const float* __restrict__ g, const float* __restrict__ be) {
    int c = threadIdx.x;
    float s = 0.f, sq = 0.f;
    for (int i = 0; i < NCHUNKS; i++) {
        s += g_part_sum[i * 256 + c];
        sq += g_part_sq[i * 256 + c];
    }
    float mean = s / (float)ROWS;
    float var = sq / (float)ROWS - mean * mean;
    float rs = rsqrtf(var + 1e-5f);
    float sc = g[c] * rs;
    g_scale[c] = sc;
    g_shift[c] = be[c] - mean * sc;
}

// ------------- normalize + relu (elementwise), bufX -> bufY -------------
__global__ void bn_relu(int srcbuf, int dstbuf, int Cmask) {
    const float* Y = buf_ptr(srcbuf);
    float* X = buf_ptr(dstbuf);
    size_t i = (size_t)blockIdx.x * blockDim.x + threadIdx.x;
    int c = (int)(i & Cmask);
    float v = Y[i] * g_scale[c] + g_shift[c];
    X[i] = fmaxf(v, 0.0f);
}

// ------------- final: normalize + relu + transpose to [B][128][N] -------------
__global__ void bn_relu_transpose_out(int srcbuf, float* __restrict__ out) {
    __shared__ float tile[32][33];
    const float* Y = buf_ptr(srcbuf);
    int b = blockIdx.z;
    int n0 = blockIdx.x * 32, c0 = blockIdx.y * 32;
    int x = threadIdx.x, y = threadIdx.y;  // (32,8)
#pragma unroll
    for (int i = 0; i < 32; i += 8) {
        int n = n0 + y + i;
        int c = c0 + x;
        float v = Y[((size_t)b * NPTS + n) * 128 + c];
        v = v * g_scale[c] + g_shift[c];
        tile[y + i][x] = fmaxf(v, 0.0f);   // tile[n_local][c_local]
    }
    __syncthreads();
#pragma unroll
    for (int i = 0; i < 32; i += 8) {
        int c = c0 + y + i;
        out[((size_t)b * 128 + c) * NPTS + n0 + x] = tile[x][y + i];
    }
}

// knn launchers writing into globals
__global__ void knn3_a(const float* __restrict__ xyz1, const float* __restrict__ xyz2) {
    // never called; placeholder to satisfy forward decl (actual work via template below)
}
__global__ void knn3_b(const float* __restrict__ xyz1, const float* __restrict__ xyz2) {
}

// wrappers binding template knn to global outputs
template <int S>
__global__ void knn3_to(const float* __restrict__ xyz1, const float* __restrict__ xyz2,
                        int which) {
    // not used
}

// Direct variants writing to globals (avoid passing device-global addresses from host)
template <int S, int WHICH>  // WHICH: 0 -> A arrays, 1 -> B arrays
__global__ void knn3_g(const float* __restrict__ xyz1, const float* __restrict__ xyz2) {
    __shared__ float rx[S], ry[S], rz[S], rsq[S];
    int b = blockIdx.y;
    int n = blockIdx.x * blockDim.x + threadIdx.x;
    const float* x2 = xyz2 + (size_t)b * 3 * S;
    for (int s = threadIdx.x; s < S; s += blockDim.x) {
        float a = x2[s], bb = x2[S + s], c = x2[2 * S + s];
        rx[s] = a; ry[s] = bb; rz[s] = c;
        rsq[s] = a * a + bb * bb + c * c;
    }
    __syncthreads();
    const float* x1 = xyz1 + (size_t)b * 3 * NPTS;
    float qx = x1[n], qy = x1[NPTS + n], qz = x1[2 * NPTS + n];
    float qn = qx * qx + qy * qy + qz * qz;
    float d0 = 1e30f, d1 = 1e30f, d2 = 1e30f;
    int i0 = 0, i1 = 0, i2 = 0;
#pragma unroll 4
    for (int s = 0; s < S; s++) {
        float dot = qx * rx[s] + qy * ry[s] + qz * rz[s];
        float d = qn + rsq[s] - 2.0f * dot;
        if (d < d2) {
            if (d < d1) {
                d2 = d1; i2 = i1;
                if (d < d0) { d1 = d0; i1 = i0; d0 = d; i0 = s; }
                else        { d1 = d;  i1 = s; }
            } else { d2 = d; i2 = s; }
        }
    }
    float r0 = 1.0f / (d0 + 1e-8f), r1 = 1.0f / (d1 + 1e-8f), r2 = 1.0f / (d2 + 1e-8f);
    float inv = 1.0f / (r0 + r1 + r2);
    size_t base = ((size_t)b * NPTS + n) * 3;
    int* idx_out = (WHICH == 0) ? g_idxA : g_idxB;
    float* w_out = (WHICH == 0) ? g_wA : g_wB;
    idx_out[base] = i0; idx_out[base + 1] = i1; idx_out[base + 2] = i2;
    w_out[base] = r0 * inv; w_out[base + 1] = r1 * inv; w_out[base + 2] = r2 * inv;
}

// ---------------- host launch ----------------
extern "C" void kernel_launch(void* const* d_in, const int* in_sizes, int n_in,
                              void* d_out, int out_size) {
    (void)in_sizes; (void)n_in; (void)out_size;
    const float* xyz1  = (const float*)d_in[0];
    const float* xyz2a = (const float*)d_in[1];
    const float* xyz2b = (const float*)d_in[2];
    const float* pts1  = (const float*)d_in[3];
    const float* pts2a = (const float*)d_in[4];
    const float* pts2b = (const float*)d_in[5];
    const float* W0 = (const float*)d_in[6];
    const float* b0 = (const float*)d_in[7];
    const float* g0 = (const float*)d_in[8];
    const float* be0 = (const float*)d_in[9];
    const float* W1 = (const float*)d_in[10];
    const float* b1 = (const float*)d_in[11];
    const float* g1 = (const float*)d_in[12];
    const float* be1 = (const float*)d_in[13];
    const float* W2 = (const float*)d_in[14];
    const float* b2 = (const float*)d_in[15];
    const float* g2 = (const float*)d_in[16];
    const float* be2 = (const float*)d_in[17];
    float* out = (float*)d_out;

    dim3 tb(32, 8);
    // points1 [B,128,N] -> x0 cols [0,128)
    transpose_cn<<<dim3(NPTS / 32, C1 / 32, BATCH), tb>>>(pts1, 0, C1, NPTS, INCH, 0);
    // points2 transposes -> [b][s][c]
    transpose_cn<<<dim3(SA / 32, C2 / 32, BATCH), tb>>>(pts2a, 1, C2, SA, C2, 0);
    transpose_cn<<<dim3(SB / 32, C2 / 32, BATCH), tb>>>(pts2b, 2, C2, SB, C2, 0);
    // 3-NN for both sources
    knn3_g<SA, 0><<<dim3(NPTS / 256, BATCH), 256>>>(xyz1, xyz2a);
    knn3_g<SB, 1><<<dim3(NPTS / 256, BATCH), 256>>>(xyz1, xyz2b);
    // weighted gather into x0 cols [128,640)
    gather_interp<<<ROWS, 256>>>();

    // Layer 0: 640 -> 256   (src -1 = g_x0, dst buf 0)
    gemm_bias<<<dim3(256 / 128, ROWS / 128), 256>>>(-1, W0, b0, 0, INCH, 256);
    bn_partial<<<NCHUNKS, 256>>>(0, 256);
    bn_finalize<<<1, 256>>>(g0, be0);
    bn_relu<<<(ROWS * 256) / 256, 256>>>(0, 1, 255);

    // Layer 1: 256 -> 256  (src buf 1, dst buf 0)
    gemm_bias<<<dim3(256 / 128, ROWS / 128), 256>>>(1, W1, b1, 0, 256, 256);
    bn_partial<<<NCHUNKS, 256>>>(0, 256);
    bn_finalize<<<1, 256>>>(g1, be1);
    bn_relu<<<(ROWS * 256) / 256, 256>>>(0, 1, 255);

    // Layer 2: 256 -> 128  (src buf 1, dst buf 0)
    gemm_bias<<<dim3(128 / 128, ROWS / 128), 256>>>(1, W2, b2, 0, 256, 128);
    bn_partial<<<NCHUNKS, 128>>>(0, 128);
    bn_finalize<<<1, 128>>>(g2, be2);
    // normalize + relu + transpose into [B,128,N] output
    bn_relu_transpose_out<<<dim3(NPTS / 32, 128 / 32, BATCH), tb>>>(0, out);
}

// round 4
// speedup vs baseline: 2.1317x; 2.1317x over previous
#include <cuda_runtime.h>
#include <cstdint>

// Problem constants
#define BATCH 8
#define NPTS  8192
#define SA    2048
#define SB    512
#define C1    128
#define C2    256
#define INCH  640    // C1 + 2*C2
#define ROWS  (BATCH * NPTS)   // 65536
#define NCHUNKS 256
#define ROWS_PER_CHUNK (ROWS / NCHUNKS)  // 256

// ---------------- scratch (device globals; no runtime alloc allowed) ----------------
__device__ float g_x0[(size_t)ROWS * INCH];
__device__ float g_bufA[(size_t)ROWS * 256];
__device__ float g_bufB[(size_t)ROWS * 256];
__device__ float g_p2at[(size_t)BATCH * SA * C2];
__device__ float g_p2bt[(size_t)BATCH * SB * C2];
__device__ int   g_idxA[(size_t)ROWS * 3];
__device__ float g_wA[(size_t)ROWS * 3];
__device__ int   g_idxB[(size_t)ROWS * 3];
__device__ float g_wB[(size_t)ROWS * 3];
__device__ float g_part_sum[NCHUNKS * 256];
__device__ float g_part_sq[NCHUNKS * 256];
__device__ float g_scale[256];
__device__ float g_shift[256];

__device__ __forceinline__ float* buf_ptr(int which) {
    return which == 0 ? g_bufA : g_bufB;
}

// ---------------- transpose [B][C][Nn] -> dst[(b*Nn+n)*ldo + co + c] ----------------
__global__ void transpose_cn(const float* __restrict__ in, int dst,
                             int C, int Nn, int ldo, int co) {
    __shared__ float tile[32][33];
    float* out = (dst == 0) ? g_x0 : (dst == 1 ? g_p2at : g_p2bt);
    int b = blockIdx.z;
    int n0 = blockIdx.x * 32;
    int c0 = blockIdx.y * 32;
    int x = threadIdx.x, y = threadIdx.y; // block (32,8)
    const float* inb = in + (size_t)b * C * Nn;
#pragma unroll
    for (int i = 0; i < 32; i += 8) {
        int c = c0 + y + i;
        tile[y + i][x] = inb[(size_t)c * Nn + n0 + x];
    }
    __syncthreads();
    float* outb = out + (size_t)b * Nn * ldo + co;
#pragma unroll
    for (int i = 0; i < 32; i += 8) {
        int n = n0 + y + i;
        outb[(size_t)n * ldo + c0 + x] = tile[x][y + i];
    }
}

// ---------------- 3-NN ----------------
template <int S, int WHICH>  // WHICH: 0 -> A arrays, 1 -> B arrays
__global__ void knn3_g(const float* __restrict__ xyz1, const float* __restrict__ xyz2) {
    __shared__ float rx[S], ry[S], rz[S], rsq[S];
    int b = blockIdx.y;
    int n = blockIdx.x * blockDim.x + threadIdx.x;
    const float* x2 = xyz2 + (size_t)b * 3 * S;
    for (int s = threadIdx.x; s < S; s += blockDim.x) {
        float a = x2[s], bb = x2[S + s], c = x2[2 * S + s];
        rx[s] = a; ry[s] = bb; rz[s] = c;
        rsq[s] = a * a + bb * bb + c * c;
    }
    __syncthreads();
    const float* x1 = xyz1 + (size_t)b * 3 * NPTS;
    float qx = x1[n], qy = x1[NPTS + n], qz = x1[2 * NPTS + n];
    float qn = qx * qx + qy * qy + qz * qz;
    float d0 = 1e30f, d1 = 1e30f, d2 = 1e30f;
    int i0 = 0, i1 = 0, i2 = 0;
#pragma unroll 4
    for (int s = 0; s < S; s++) {
        float dot = qx * rx[s] + qy * ry[s] + qz * rz[s];
        float d = qn + rsq[s] - 2.0f * dot;
        if (d < d2) {
            if (d < d1) {
                d2 = d1; i2 = i1;
                if (d < d0) { d1 = d0; i1 = i0; d0 = d; i0 = s; }
                else        { d1 = d;  i1 = s; }
            } else { d2 = d; i2 = s; }
        }
    }
    float r0 = 1.0f / (d0 + 1e-8f), r1 = 1.0f / (d1 + 1e-8f), r2 = 1.0f / (d2 + 1e-8f);
    float inv = 1.0f / (r0 + r1 + r2);
    size_t base = ((size_t)b * NPTS + n) * 3;
    int* idx_out = (WHICH == 0) ? g_idxA : g_idxB;
    float* w_out = (WHICH == 0) ? g_wA : g_wB;
    idx_out[base] = i0; idx_out[base + 1] = i1; idx_out[base + 2] = i2;
    w_out[base] = r0 * inv; w_out[base + 1] = r1 * inv; w_out[base + 2] = r2 * inv;
}

// ------------- gather: weighted 3-NN feature sums into x0 cols [128,640) -------------
__global__ void gather_interp() {
    int r = blockIdx.x;
    int c = threadIdx.x;          // 0..255
    int b = r / NPTS;
    size_t nb = (size_t)r * 3;
    int ib0 = g_idxB[nb], ib1 = g_idxB[nb + 1], ib2 = g_idxB[nb + 2];
    float vb0 = g_wB[nb], vb1 = g_wB[nb + 1], vb2 = g_wB[nb + 2];
    int ia0 = g_idxA[nb], ia1 = g_idxA[nb + 1], ia2 = g_idxA[nb + 2];
    float va0 = g_wA[nb], va1 = g_wA[nb + 1], va2 = g_wA[nb + 2];
    const float* pb = g_p2bt + (size_t)b * SB * C2;
    const float* pa = g_p2at + (size_t)b * SA * C2;
    float ob = vb0 * pb[(size_t)ib0 * C2 + c] + vb1 * pb[(size_t)ib1 * C2 + c]
             + vb2 * pb[(size_t)ib2 * C2 + c];
    float oa = va0 * pa[(size_t)ia0 * C2 + c] + va1 * pa[(size_t)ia1 * C2 + c]
             + va2 * pa[(size_t)ia2 * C2 + c];
    size_t rb = (size_t)r * INCH;
    g_x0[rb + C1 + c]      = ob;
    g_x0[rb + C1 + C2 + c] = oa;
}

// ------------- TF32 tensor-core GEMM: Y[M,Ncols] = X[M,K] @ W[Ncols,K]^T + bias ------
// Block tile 128x128, BK=32, 8 warps (4m x 2n), warp tile 32x64.
// mma.sync.m16n8k8 tf32. Optional fused BN(prev layer)+ReLU on X load.
#define SKX 36   // smem row stride in floats: 36 % 32 == 4 -> conflict-free frags + stores

__device__ __forceinline__ uint32_t f2tf32(float f) {
    uint32_t r;
    asm("cvt.rna.tf32.f32 %0, %1;" : "=r"(r) : "f"(f));
    return r;
}

__device__ __forceinline__ void mma_tf32(float* d, const uint32_t* a, const uint32_t* b) {
    asm volatile(
        "mma.sync.aligned.m16n8k8.row.col.f32.tf32.tf32.f32 "
        "{%0,%1,%2,%3}, {%4,%5,%6,%7}, {%8,%9}, {%0,%1,%2,%3};\n"
        : "+f"(d[0]), "+f"(d[1]), "+f"(d[2]), "+f"(d[3])
        : "r"(a[0]), "r"(a[1]), "r"(a[2]), "r"(a[3]), "r"(b[0]), "r"(b[1]));
}

__global__ __launch_bounds__(256, 2)
void gemm_tf32(int src, const float* __restrict__ W,
               const float* __restrict__ bias, int dstbuf,
               int K, int Ncols, int fuse) {
    __shared__ uint32_t Xs[128][SKX];
    __shared__ uint32_t Ws[128][SKX];
    __shared__ float sc[256], sh[256];
    const float* X = (src < 0) ? g_x0 : buf_ptr(src);
    float* Y = buf_ptr(dstbuf);
    int tid = threadIdx.x;
    if (fuse && tid < K) { sc[tid] = g_scale[tid]; sh[tid] = g_shift[tid]; }
    __syncthreads();

    int row0 = blockIdx.y * 128;
    int col0 = blockIdx.x * 128;
    int lrow = tid >> 3;              // 0..31
    int lc4  = (tid & 7) * 4;         // 0,4,...,28
    int warp = tid >> 5, lane = tid & 31;
    int wm = warp >> 1, wn = warp & 1;
    int m_base = wm * 32, n_base = wn * 64;
    int grp = lane >> 2, qid = lane & 3;

    float acc[2][8][4];
#pragma unroll
    for (int mt = 0; mt < 2; mt++)
#pragma unroll
        for (int nt = 0; nt < 8; nt++)
#pragma unroll
            for (int i = 0; i < 4; i++) acc[mt][nt][i] = 0.0f;

    const float* Xbase = X + (size_t)row0 * K;
    const float* Wbase = W + (size_t)col0 * K;

    for (int k0 = 0; k0 < K; k0 += 32) {
        // ---- load X,W tiles (coalesced float4), convert to tf32, optional BN+ReLU ----
#pragma unroll
        for (int p = 0; p < 4; p++) {
            int r = lrow + 32 * p;
            float4 xv = *(const float4*)(Xbase + (size_t)r * K + k0 + lc4);
            if (fuse) {
                int c = k0 + lc4;
                xv.x = fmaxf(xv.x * sc[c]     + sh[c],     0.f);
                xv.y = fmaxf(xv.y * sc[c + 1] + sh[c + 1], 0.f);
                xv.z = fmaxf(xv.z * sc[c + 2] + sh[c + 2], 0.f);
                xv.w = fmaxf(xv.w * sc[c + 3] + sh[c + 3], 0.f);
            }
            Xs[r][lc4 + 0] = f2tf32(xv.x);
            Xs[r][lc4 + 1] = f2tf32(xv.y);
            Xs[r][lc4 + 2] = f2tf32(xv.z);
            Xs[r][lc4 + 3] = f2tf32(xv.w);
            float4 wv = *(const float4*)(Wbase + (size_t)r * K + k0 + lc4);
            Ws[r][lc4 + 0] = f2tf32(wv.x);
            Ws[r][lc4 + 1] = f2tf32(wv.y);
            Ws[r][lc4 + 2] = f2tf32(wv.z);
            Ws[r][lc4 + 3] = f2tf32(wv.w);
        }
        __syncthreads();
        // ---- compute: 4 k8-steps ----
#pragma unroll
        for (int kk = 0; kk < 4; kk++) {
            int kf = kk * 8;
            uint32_t a[2][4];
#pragma unroll
            for (int mt = 0; mt < 2; mt++) {
                int ra = m_base + mt * 16 + grp;
                a[mt][0] = Xs[ra][kf + qid];
                a[mt][1] = Xs[ra + 8][kf + qid];
                a[mt][2] = Xs[ra][kf + qid + 4];
                a[mt][3] = Xs[ra + 8][kf + qid + 4];
            }
            uint32_t bf[8][2];
#pragma unroll
            for (int nt = 0; nt < 8; nt++) {
                int cb = n_base + nt * 8 + grp;
                bf[nt][0] = Ws[cb][kf + qid];
                bf[nt][1] = Ws[cb][kf + qid + 4];
            }
#pragma unroll
            for (int mt = 0; mt < 2; mt++)
#pragma unroll
                for (int nt = 0; nt < 8; nt++)
                    mma_tf32(acc[mt][nt], a[mt], bf[nt]);
        }
        __syncthreads();
    }

    // ---- epilogue: + bias, store fp32 ----
#pragma unroll
    for (int mt = 0; mt < 2; mt++) {
        int rA = row0 + m_base + mt * 16 + grp;
#pragma unroll
        for (int nt = 0; nt < 8; nt++) {
            int cA = col0 + n_base + nt * 8 + qid * 2;
            float b0v = bias[cA], b1v = bias[cA + 1];
            float2 v0 = make_float2(acc[mt][nt][0] + b0v, acc[mt][nt][1] + b1v);
            float2 v1 = make_float2(acc[mt][nt][2] + b0v, acc[mt][nt][3] + b1v);
            *(float2*)&Y[(size_t)rA * Ncols + cA] = v0;
            *(float2*)&Y[(size_t)(rA + 8) * Ncols + cA] = v1;
        }
    }
}

// ------------- BN stats, deterministic 2-stage reduction -------------
__global__ void bn_partial(int srcbuf, int C) {
    const float* Y = buf_ptr(srcbuf);
    int c = threadIdx.x;
    int chunk = blockIdx.x;
    size_t r0 = (size_t)chunk * ROWS_PER_CHUNK;
    float s = 0.f, sq = 0.f;
    for (int i = 0; i < ROWS_PER_CHUNK; i++) {
        float v = Y[(r0 + i) * C + c];
        s += v; sq += v * v;
    }
    g_part_sum[chunk * 256 + c] = s;
    g_part_sq[chunk * 256 + c] = sq;
}

__global__ void bn_finalize(const float* __restrict__ g, const float* __restrict__ be) {
    int c = threadIdx.x;
    float s = 0.f, sq = 0.f;
    for (int i = 0; i < NCHUNKS; i++) {
        s += g_part_sum[i * 256 + c];
        sq += g_part_sq[i * 256 + c];
    }
    float mean = s / (float)ROWS;
    float var = sq / (float)ROWS - mean * mean;
    float rs = rsqrtf(var + 1e-5f);
    float scv = g[c] * rs;
    g_scale[c] = scv;
    g_shift[c] = be[c] - mean * scv;
}

// ------------- final: normalize + relu + transpose to [B][128][N] -------------
__global__ void bn_relu_transpose_out(int srcbuf, float* __restrict__ out) {
    __shared__ float tile[32][33];
    const float* Y = buf_ptr(srcbuf);
    int b = blockIdx.z;
    int n0 = blockIdx.x * 32, c0 = blockIdx.y * 32;
    int x = threadIdx.x, y = threadIdx.y;  // (32,8)
#pragma unroll
    for (int i = 0; i < 32; i += 8) {
        int n = n0 + y + i;
        int c = c0 + x;
        float v = Y[((size_t)b * NPTS + n) * 128 + c];
        v = v * g_scale[c] + g_shift[c];
        tile[y + i][x] = fmaxf(v, 0.0f);
    }
    __syncthreads();
#pragma unroll
    for (int i = 0; i < 32; i += 8) {
        int c = c0 + y + i;
        out[((size_t)b * 128 + c) * NPTS + n0 + x] = tile[x][y + i];
    }
}

// ---------------- host launch ----------------
extern "C" void kernel_launch(void* const* d_in, const int* in_sizes, int n_in,
                              void* d_out, int out_size) {
    (void)in_sizes; (void)n_in; (void)out_size;
    const float* xyz1  = (const float*)d_in[0];
    const float* xyz2a = (const float*)d_in[1];
    const float* xyz2b = (const float*)d_in[2];
    const float* pts1  = (const float*)d_in[3];
    const float* pts2a = (const float*)d_in[4];
    const float* pts2b = (const float*)d_in[5];
    const float* W0 = (const float*)d_in[6];
    const float* b0 = (const float*)d_in[7];
    const float* g0 = (const float*)d_in[8];
    const float* be0 = (const float*)d_in[9];
    const float* W1 = (const float*)d_in[10];
    const float* b1 = (const float*)d_in[11];
    const float* g1 = (const float*)d_in[12];
    const float* be1 = (const float*)d_in[13];
    const float* W2 = (const float*)d_in[14];
    const float* b2 = (const float*)d_in[15];
    const float* g2 = (const float*)d_in[16];
    const float* be2 = (const float*)d_in[17];
    float* out = (float*)d_out;

    dim3 tb(32, 8);
    transpose_cn<<<dim3(NPTS / 32, C1 / 32, BATCH), tb>>>(pts1, 0, C1, NPTS, INCH, 0);
    transpose_cn<<<dim3(SA / 32, C2 / 32, BATCH), tb>>>(pts2a, 1, C2, SA, C2, 0);
    transpose_cn<<<dim3(SB / 32, C2 / 32, BATCH), tb>>>(pts2b, 2, C2, SB, C2, 0);
    knn3_g<SA, 0><<<dim3(NPTS / 256, BATCH), 256>>>(xyz1, xyz2a);
    knn3_g<SB, 1><<<dim3(NPTS / 256, BATCH), 256>>>(xyz1, xyz2b);
    gather_interp<<<ROWS, 256>>>();

    // Layer 0: 640 -> 256 ; X = g_x0 (no fuse) -> bufA
    gemm_tf32<<<dim3(256 / 128, ROWS / 128), 256>>>(-1, W0, b0, 0, INCH, 256, 0);
    bn_partial<<<NCHUNKS, 256>>>(0, 256);
    bn_finalize<<<1, 256>>>(g0, be0);

    // Layer 1: 256 -> 256 ; X = bufA with fused BN0+ReLU -> bufB
    gemm_tf32<<<dim3(256 / 128, ROWS / 128), 256>>>(0, W1, b1, 1, 256, 256, 1);
    bn_partial<<<NCHUNKS, 256>>>(1, 256);
    bn_finalize<<<1, 256>>>(g1, be1);

    // Layer 2: 256 -> 128 ; X = bufB with fused BN1+ReLU -> bufA
    gemm_tf32<<<dim3(128 / 128, ROWS / 128), 256>>>(1, W2, b2, 0, 256, 128, 1);
    bn_partial<<<NCHUNKS, 128>>>(0, 128);
    bn_finalize<<<1, 128>>>(g2, be2);

    // normalize + relu + transpose into [B,128,N] output
    bn_relu_transpose_out<<<dim3(NPTS / 32, 128 / 32, BATCH), tb>>>(0, out);
}